// round 13
// baseline (speedup 1.0000x reference)
#include <cuda_runtime.h>
#include <cuda_bf16.h>
#include <math.h>

// T=2048 tokens, H=2048 hidden, V=32000 vocab, E=16 experts, top-2.
// Inputs: hidden_states (T*H f32), gate_w (16*H f32), expert_biases (16*V f32).
// Output: bias (T*V f32) then aux_loss (1 f32).
//
// Single fused kernel: gate blocks (low bids, wave 1) produce g_meta and
// signal per-token-group counters; bias blocks stage smem, then wait only for
// their own group's 16 gate blocks. Gate latency hides under bias stores.

#define NUM_E 16
#define MAX_T 8192
#define CHUNK_F4 128          // 512 floats = 2048 B per expert per chunk
#define TOK_GRP  128

__device__ float  g_probs[MAX_T * NUM_E];   // softmax probs per token
__device__ float4 g_meta[MAX_T];            // (w0, w1, bitcast i0, bitcast i1)
__device__ int    g_grp_cnt[MAX_T / TOK_GRP];
__device__ int    g_tot_cnt;

// ---------------------------------------------------------------------------
__global__ void reset_kernel(int ngrp)
{
    if (threadIdx.x < ngrp) g_grp_cnt[threadIdx.x] = 0;
    if (threadIdx.x == 31)  g_tot_cnt = 0;
}

// ---------------------------------------------------------------------------
// Fused kernel. bid < nbGate: gate path (8 tokens per block; warp =
// token-quad x H-quarter, 2048 warps chip-wide). Else: bias path.
// ---------------------------------------------------------------------------
__global__ __launch_bounds__(256, 2) void fused_kernel(
    const float* __restrict__ hidden,
    const float* __restrict__ gate_w,
    const float* __restrict__ biases,
    float* __restrict__ out,
    float* __restrict__ out_aux,
    int H, int V, int T)
{
    __shared__ __align__(16) char smem_raw[39040];

    const int tid  = threadIdx.x;
    const int bid  = blockIdx.x;
    const int nbGate = T >> 3;             // 256

    if (bid < nbGate) {
        // =================== GATE PATH ===================
        float (*red)[2][4][NUM_E] = (float (*)[2][4][NUM_E])smem_raw;  // [4][2][4][16]
        float (*slog)[NUM_E]      = (float (*)[NUM_E])(smem_raw + 2048);

        const int lane = tid & 31;
        const int warp = tid >> 5;
        const int tq   = warp & 1;          // token quad (0/1)
        const int sl   = warp >> 1;         // H quarter (0..3)
        const int Hf4  = H >> 2;            // 512
        const int qf4  = Hf4 >> 2;          // 128
        const int tok0 = bid * 8 + tq * 4;

        const float4* __restrict__ hf4 = (const float4*)hidden;
        const float4* __restrict__ gf4 = (const float4*)gate_w;

        float acc[NUM_E][4];
        #pragma unroll
        for (int e = 0; e < NUM_E; e++)
            #pragma unroll
            for (int t = 0; t < 4; t++) acc[e][t] = 0.0f;

        const int pbase = sl * qf4 + lane;

        #pragma unroll
        for (int c = 0; c < 2; c++) {
            float4 h[4][2];
            #pragma unroll
            for (int t = 0; t < 4; t++)
                #pragma unroll
                for (int jj = 0; jj < 2; jj++)
                    h[t][jj] = hf4[(size_t)(tok0 + t) * Hf4 + pbase + (c*2 + jj)*32];

            #pragma unroll
            for (int jj = 0; jj < 2; jj++) {
                const int pos = pbase + (c*2 + jj)*32;
                #pragma unroll
                for (int e = 0; e < NUM_E; e++) {
                    float4 g = __ldg(&gf4[(size_t)e * Hf4 + pos]);
                    #pragma unroll
                    for (int t = 0; t < 4; t++)
                        acc[e][t] += h[t][jj].x*g.x + h[t][jj].y*g.y
                                   + h[t][jj].z*g.z + h[t][jj].w*g.w;
                }
            }
        }

        #pragma unroll
        for (int e = 0; e < NUM_E; e++) {
            #pragma unroll
            for (int t = 0; t < 4; t++) {
                float v = acc[e][t];
                #pragma unroll
                for (int s = 16; s > 0; s >>= 1)
                    v += __shfl_xor_sync(0xffffffffu, v, s);
                if (lane == 0) red[sl][tq][t][e] = v;
            }
        }
        __syncthreads();

        if (tid < 128) {
            const int t8 = tid >> 4;
            const int e  = tid & 15;
            const int q  = t8 >> 2, ti = t8 & 3;
            slog[t8][e] = red[0][q][ti][e] + red[1][q][ti][e]
                        + red[2][q][ti][e] + red[3][q][ti][e];
        }
        __syncthreads();

        if (tid < 8) {
            const int tok = bid * 8 + tid;
            float l[NUM_E];
            #pragma unroll
            for (int e = 0; e < NUM_E; e++) l[e] = slog[tid][e];

            float mx = -1e30f;
            #pragma unroll
            for (int e = 0; e < NUM_E; e++) mx = fmaxf(mx, l[e]);
            float p[NUM_E];
            float sum = 0.0f;
            #pragma unroll
            for (int e = 0; e < NUM_E; e++) { p[e] = expf(l[e] - mx); sum += p[e]; }
            float inv = 1.0f / sum;

            int   i0 = 0, i1 = -1;
            float p0 = -1.0f, p1 = -1.0f;
            float pr[NUM_E];
            #pragma unroll
            for (int e = 0; e < NUM_E; e++) {
                float pe = p[e] * inv;
                pr[e] = pe;
                if (pe > p0)      { p1 = p0; i1 = i0; p0 = pe; i0 = e; }
                else if (pe > p1) { p1 = pe; i1 = e; }
            }
            float4* probs4 = (float4*)&g_probs[(size_t)tok * NUM_E];
            #pragma unroll
            for (int c = 0; c < 4; c++)
                probs4[c] = make_float4(pr[c*4], pr[c*4+1], pr[c*4+2], pr[c*4+3]);

            float s2 = p0 + p1;
            float4 m;
            m.x = p0 / s2;
            m.y = p1 / s2;
            m.z = __int_as_float(i0);
            m.w = __int_as_float(i1);
            g_meta[tok] = m;
        }

        // signal: this block's 8 tokens are ready
        __syncthreads();
        if (tid == 0) {
            __threadfence();
            atomicAdd(&g_grp_cnt[bid >> 4], 1);   // 16 gate blocks per group
            atomicAdd(&g_tot_cnt, 1);
        }
        return;
    }

    // =================== BIAS PATH ===================
    float4 (*sB)[CHUNK_F4] = (float4 (*)[CHUNK_F4])smem_raw;            // 32 KB
    float4* smeta = (float4*)(smem_raw + 32768);                        // 2 KB
    float4* s4    = (float4*)(smem_raw + 34816);                        // 4 KB
    float4* su4   = (float4*)(smem_raw + 38912);                        // 64 B

    const int nchunks = (V / 4 + CHUNK_F4 - 1) / CHUNK_F4;   // 63
    const int i    = bid - nbGate;
    const int bx   = i % nchunks;                  // v-chunk
    const int by   = i / nchunks;                  // token group
    const int lane = tid & 31;
    const int warp = tid >> 5;
    const int Vf4  = V >> 2;                       // 8000
    const int vbase = bx * CHUNK_F4;               // 2048B-aligned
    const int clen  = min(CHUNK_F4, Vf4 - vbase);  // 128 or 64 (tail)
    const int tbase = by * TOK_GRP;

    const float4* __restrict__ bf4 = (const float4*)biases;
    float4* __restrict__ of4 = (float4*)out;

    // stage sB (independent of gating — overlaps the gate tail)
    for (int k = tid; k < NUM_E * CHUNK_F4; k += 256) {
        int e = k >> 7, p = k & (CHUNK_F4 - 1);
        if (p < clen) sB[e][p] = bf4[(size_t)e * Vf4 + vbase + p];
    }

    // wait for this token group's gating to be complete
    if (tid == 0) {
        while (atomicAdd(&g_grp_cnt[by], 0) < 16) __nanosleep(64);
        __threadfence();
    }
    __syncthreads();

    if (tid < TOK_GRP) smeta[tid] = g_meta[tbase + tid];
    __syncthreads();

    // warp-per-token, lane-contiguous 16B streaming stores
    for (int t = warp; t < TOK_GRP; t += 8) {
        float4 m = smeta[t];
        const float w0 = m.x, w1 = m.y;
        const int i0 = __float_as_int(m.z);
        const int i1 = __float_as_int(m.w);
        float4* __restrict__ orow = &of4[(size_t)(tbase + t) * Vf4 + vbase];
        #pragma unroll 4
        for (int p = lane; p < clen; p += 32) {
            float4 a = sB[i0][p];
            float4 b = sB[i1][p];
            float4 r;
            r.x = w0 * a.x + w1 * b.x;
            r.y = w0 * a.y + w1 * b.y;
            r.z = w0 * a.z + w1 * b.z;
            r.w = w0 * a.w + w1 * b.w;
            __stcs(&orow[p], r);
        }
    }

    // ---- aux loss: first bias block, after all gating done ----
    if (i == 0) {
        if (tid == 0) {
            while (atomicAdd(&g_tot_cnt, 0) < nbGate) __nanosleep(64);
            __threadfence();
        }
        __syncthreads();

        const int e4 = tid & 3;
        const int c  = tid >> 2;
        const float4* __restrict__ probs4 = (const float4*)g_probs;

        float4 sum = make_float4(0.f, 0.f, 0.f, 0.f);
        for (int t = c; t < T; t += 64) {
            float4 v = probs4[(size_t)t * 4 + e4];
            sum.x += v.x; sum.y += v.y; sum.z += v.z; sum.w += v.w;
        }
        s4[tid] = sum;
        __syncthreads();

        if (tid < 4) {
            float4 u = make_float4(0.f, 0.f, 0.f, 0.f);
            #pragma unroll
            for (int cc = 0; cc < 64; cc++) {
                float4 v = s4[cc * 4 + tid];
                u.x += v.x; u.y += v.y; u.z += v.z; u.w += v.w;
            }
            su4[tid] = u;
        }
        __syncthreads();

        if (tid == 0) {
            float invT = 1.0f / (float)T;
            float aux = 0.0f;
            #pragma unroll
            for (int q = 0; q < 4; q++) {
                float4 u = su4[q];
                float a = u.x * invT, b = u.y * invT;
                float cc = u.z * invT, d = u.w * invT;
                aux += a * logf(a) + b * logf(b) + cc * logf(cc) + d * logf(d);
            }
            out_aux[0] = aux * (float)NUM_E;
        }
    }
}

// ---------------------------------------------------------------------------
extern "C" void kernel_launch(void* const* d_in, const int* in_sizes, int n_in,
                              void* d_out, int out_size)
{
    const float* hidden = (const float*)d_in[0];
    const float* gate_w = (const float*)d_in[1];
    const float* biases = (const float*)d_in[2];
    float* out = (float*)d_out;

    const int H = in_sizes[1] / NUM_E;         // 2048
    const int T = in_sizes[0] / H;             // 2048
    const int V = in_sizes[2] / NUM_E;         // 32000

    const int nbGate  = T / 8;                            // 256
    const int nchunks = (V / 4 + CHUNK_F4 - 1) / CHUNK_F4; // 63
    const int ngrp    = T / TOK_GRP;                      // 16

    reset_kernel<<<1, 32>>>(ngrp);
    fused_kernel<<<nbGate + nchunks * ngrp, 256>>>(
        hidden, gate_w, biases, out, out + (size_t)T * V, H, V, T);
}

// round 14
// speedup vs baseline: 1.1535x; 1.1535x over previous
#include <cuda_runtime.h>
#include <cuda_bf16.h>
#include <math.h>

// T=2048 tokens, H=2048 hidden, V=32000 vocab, E=16 experts, top-2.
// Inputs: hidden_states (T*H f32), gate_w (16*H f32), expert_biases (16*V f32).
// Output: bias (T*V f32) then aux_loss (1 f32).
//
// Two kernels, overlapped via PDL: gate (R12 quad layout) triggers
// programmatic completion; bias launches with programmatic stream
// serialization, stages its expert chunk BEFORE cudaGridDependencySynchronize,
// so staging overlaps the gate tail. Registers stay decoupled (the R13 bug).

#define NUM_E 16
#define MAX_T 8192
#define CHUNK_F4 128          // 512 floats = 2048 B per expert per chunk
#define TOK_GRP  128

__device__ float  g_probs[MAX_T * NUM_E];   // softmax probs per token
__device__ float4 g_meta[MAX_T];            // (w0, w1, bitcast i0, bitcast i1)

// ---------------------------------------------------------------------------
// Gate: warp = (token-quad) x (H-quarter), 8 tokens/block, 2048 warps.
// ---------------------------------------------------------------------------
__global__ __launch_bounds__(256, 2) void gate_kernel(
    const float* __restrict__ hidden,
    const float* __restrict__ gate_w,
    int H)
{
    const int tid  = threadIdx.x;
    const int lane = tid & 31;
    const int warp = tid >> 5;
    const int tq   = warp & 1;          // token quad (0/1)
    const int sl   = warp >> 1;         // H quarter (0..3)
    const int Hf4  = H >> 2;            // 512
    const int qf4  = Hf4 >> 2;          // 128
    const int tok0 = blockIdx.x * 8 + tq * 4;

    const float4* __restrict__ hf4 = (const float4*)hidden;
    const float4* __restrict__ gf4 = (const float4*)gate_w;

    __shared__ float red[4][2][4][NUM_E];
    __shared__ float slog[8][NUM_E];

    float acc[NUM_E][4];
    #pragma unroll
    for (int e = 0; e < NUM_E; e++)
        #pragma unroll
        for (int t = 0; t < 4; t++) acc[e][t] = 0.0f;

    const int pbase = sl * qf4 + lane;

    #pragma unroll
    for (int c = 0; c < 2; c++) {
        float4 h[4][2];
        #pragma unroll
        for (int t = 0; t < 4; t++)
            #pragma unroll
            for (int jj = 0; jj < 2; jj++)
                h[t][jj] = hf4[(size_t)(tok0 + t) * Hf4 + pbase + (c*2 + jj)*32];

        #pragma unroll
        for (int jj = 0; jj < 2; jj++) {
            const int pos = pbase + (c*2 + jj)*32;
            #pragma unroll
            for (int e = 0; e < NUM_E; e++) {
                float4 g = __ldg(&gf4[(size_t)e * Hf4 + pos]);
                #pragma unroll
                for (int t = 0; t < 4; t++)
                    acc[e][t] += h[t][jj].x*g.x + h[t][jj].y*g.y
                               + h[t][jj].z*g.z + h[t][jj].w*g.w;
            }
        }
    }

    #pragma unroll
    for (int e = 0; e < NUM_E; e++) {
        #pragma unroll
        for (int t = 0; t < 4; t++) {
            float v = acc[e][t];
            #pragma unroll
            for (int s = 16; s > 0; s >>= 1)
                v += __shfl_xor_sync(0xffffffffu, v, s);
            if (lane == 0) red[sl][tq][t][e] = v;
        }
    }
    __syncthreads();

    if (tid < 128) {
        const int t8 = tid >> 4;
        const int e  = tid & 15;
        const int q  = t8 >> 2, ti = t8 & 3;
        slog[t8][e] = red[0][q][ti][e] + red[1][q][ti][e]
                    + red[2][q][ti][e] + red[3][q][ti][e];
    }
    __syncthreads();

    if (tid < 8) {
        const int tok = blockIdx.x * 8 + tid;
        float l[NUM_E];
        #pragma unroll
        for (int e = 0; e < NUM_E; e++) l[e] = slog[tid][e];

        float mx = -1e30f;
        #pragma unroll
        for (int e = 0; e < NUM_E; e++) mx = fmaxf(mx, l[e]);
        float p[NUM_E];
        float sum = 0.0f;
        #pragma unroll
        for (int e = 0; e < NUM_E; e++) { p[e] = expf(l[e] - mx); sum += p[e]; }
        float inv = 1.0f / sum;

        int   i0 = 0, i1 = -1;
        float p0 = -1.0f, p1 = -1.0f;
        float pr[NUM_E];
        #pragma unroll
        for (int e = 0; e < NUM_E; e++) {
            float pe = p[e] * inv;
            pr[e] = pe;
            if (pe > p0)      { p1 = p0; i1 = i0; p0 = pe; i0 = e; }
            else if (pe > p1) { p1 = pe; i1 = e; }
        }
        float4* probs4 = (float4*)&g_probs[(size_t)tok * NUM_E];
        #pragma unroll
        for (int c = 0; c < 4; c++)
            probs4[c] = make_float4(pr[c*4], pr[c*4+1], pr[c*4+2], pr[c*4+3]);

        float s2 = p0 + p1;
        float4 m;
        m.x = p0 / s2;
        m.y = p1 / s2;
        m.z = __int_as_float(i0);
        m.w = __int_as_float(i1);
        g_meta[tok] = m;
    }

#if __CUDA_ARCH__ >= 900
    cudaTriggerProgrammaticLaunchCompletion();
#endif
}

// ---------------------------------------------------------------------------
// Bias = w0*B[i0] + w1*B[i1] (262 MB stores, write-bound). PDL secondary:
// stage sB FIRST (overlaps gate tail), then grid-dependency-sync, then blend.
// Aux scratch is unioned into sB (used only after the store loop) -> smem
// 34.9 KB, 5 CTAs/SM.
// ---------------------------------------------------------------------------
__global__ __launch_bounds__(256, 5) void bias_kernel(
    const float* __restrict__ biases,
    float* __restrict__ out,
    float* __restrict__ out_aux,
    int V, int T)
{
    __shared__ float4 sB[NUM_E][CHUNK_F4];   // 32 KB (reused for aux scratch)
    __shared__ float4 smeta[TOK_GRP];        // 2 KB

    const int tid   = threadIdx.x;
    const int lane  = tid & 31;
    const int warp  = tid >> 5;
    const int Vf4   = V >> 2;                       // 8000
    const int vbase = blockIdx.x * CHUNK_F4;        // 2048B-aligned
    const int clen  = min(CHUNK_F4, Vf4 - vbase);   // 128 or 64 (tail)
    const int tbase = blockIdx.y * TOK_GRP;

    const float4* __restrict__ bf4 = (const float4*)biases;
    float4* __restrict__ of4 = (float4*)out;

    // stage sB — independent of gate results; overlaps the gate kernel
    for (int i = tid; i < NUM_E * CHUNK_F4; i += 256) {
        int e = i >> 7, p = i & (CHUNK_F4 - 1);
        if (p < clen) sB[e][p] = bf4[(size_t)e * Vf4 + vbase + p];
    }

#if __CUDA_ARCH__ >= 900
    cudaGridDependencySynchronize();     // wait for gate kernel's g_meta/g_probs
#endif

    if (tid < TOK_GRP) smeta[tid] = g_meta[tbase + tid];
    __syncthreads();

    // warp-per-token, lane-contiguous 16B streaming stores
    for (int t = warp; t < TOK_GRP; t += 8) {
        float4 m = smeta[t];
        const float w0 = m.x, w1 = m.y;
        const int i0 = __float_as_int(m.z);
        const int i1 = __float_as_int(m.w);
        float4* __restrict__ orow = &of4[(size_t)(tbase + t) * Vf4 + vbase];
        #pragma unroll 4
        for (int p = lane; p < clen; p += 32) {
            float4 a = sB[i0][p];
            float4 b = sB[i1][p];
            float4 r;
            r.x = w0 * a.x + w1 * b.x;
            r.y = w0 * a.y + w1 * b.y;
            r.z = w0 * a.z + w1 * b.z;
            r.w = w0 * a.w + w1 * b.w;
            __stcs(&orow[p], r);
        }
    }

    // ---- aux loss in block (0,0); reuse sB as scratch after store loop ----
    if (blockIdx.x == 0 && blockIdx.y == 0) {
        __syncthreads();                       // sB reads done
        float4* s4  = &sB[0][0];               // 256 float4
        float4* su4 = &sB[4][0];               // 4 float4

        const int e4 = tid & 3;
        const int c  = tid >> 2;
        const float4* __restrict__ probs4 = (const float4*)g_probs;

        float4 sum = make_float4(0.f, 0.f, 0.f, 0.f);
        for (int t = c; t < T; t += 64) {
            float4 v = probs4[(size_t)t * 4 + e4];
            sum.x += v.x; sum.y += v.y; sum.z += v.z; sum.w += v.w;
        }
        s4[tid] = sum;
        __syncthreads();

        if (tid < 4) {
            float4 u = make_float4(0.f, 0.f, 0.f, 0.f);
            #pragma unroll
            for (int cc = 0; cc < 64; cc++) {
                float4 v = s4[cc * 4 + tid];
                u.x += v.x; u.y += v.y; u.z += v.z; u.w += v.w;
            }
            su4[tid] = u;
        }
        __syncthreads();

        if (tid == 0) {
            float invT = 1.0f / (float)T;
            float aux = 0.0f;
            #pragma unroll
            for (int q = 0; q < 4; q++) {
                float4 u = su4[q];
                float a = u.x * invT, b = u.y * invT;
                float cc = u.z * invT, d = u.w * invT;
                aux += a * logf(a) + b * logf(b) + cc * logf(cc) + d * logf(d);
            }
            out_aux[0] = aux * (float)NUM_E;
        }
    }
}

// ---------------------------------------------------------------------------
extern "C" void kernel_launch(void* const* d_in, const int* in_sizes, int n_in,
                              void* d_out, int out_size)
{
    const float* hidden = (const float*)d_in[0];
    const float* gate_w = (const float*)d_in[1];
    const float* biases = (const float*)d_in[2];
    float* out = (float*)d_out;

    const int H = in_sizes[1] / NUM_E;         // 2048
    const int T = in_sizes[0] / H;             // 2048
    const int V = in_sizes[2] / NUM_E;         // 32000

    // 1) gate
    gate_kernel<<<T / 8, 256>>>(hidden, gate_w, H);

    // 2) bias, PDL-overlapped with the gate
    const int nchunks = (V / 4 + CHUNK_F4 - 1) / CHUNK_F4;   // 63
    float* out_aux = out + (size_t)T * V;

    cudaLaunchConfig_t cfg = {};
    cfg.gridDim  = dim3(nchunks, T / TOK_GRP, 1);            // (63, 16)
    cfg.blockDim = dim3(256, 1, 1);
    cfg.dynamicSmemBytes = 0;
    cfg.stream = 0;
    cudaLaunchAttribute attrs[1];
    attrs[0].id = cudaLaunchAttributeProgrammaticStreamSerialization;
    attrs[0].val.programmaticStreamSerializationAllowed = 1;
    cfg.attrs = attrs;
    cfg.numAttrs = 1;

    cudaError_t err = cudaLaunchKernelEx(&cfg, bias_kernel,
                                         biases, out, out_aux, V, T);
    if (err != cudaSuccess) {
        // fallback: plain serial launch (identical semantics)
        bias_kernel<<<dim3(nchunks, T / TOK_GRP), 256>>>(biases, out, out_aux, V, T);
    }
}